// round 13
// baseline (speedup 1.0000x reference)
#include <cuda_runtime.h>
#include <cuda_fp16.h>
#include <cstdint>

// ---------------- problem constants ----------------
#define BB   2048
#define HB   1024           // half batch
#define MAXN 16
#define NVTT 8
#define HS   501
#define VS   517
#define HP   512            // padded HS = K of all GEMMs (fp16 single-pass)
#define N1P  1536           // 3 gates * 512 (gate-major rows)
#define N2P  1024           // 2 * 512
#define NZ   56

// ---------------- device scratch ----------------
__device__ __half d_A2[BB * HP];           // fp16 activation operand
__device__ __half d_Whh2[N1P * HP];        // fp16 w_hh (gate-major rows, padded)
__device__ __half d_W22[N2P * HP];         // fp16 [gate_w_h ; map_w_h]
__device__ float  d_Hin[BB * HP];
__device__ float  d_GH[BB * N1P];
__device__ float  d_hv[BB * HP];
__device__ float  d_GM[BB * N2P];
__device__ float  d_M[BB * MAXN * HS];
__device__ float4 d_WIB[NVTT * HP];        // {w_r+bi_r+bh_r, w_z+bi_z+bh_z, w_n+bi_n, bh_n}
__device__ float2 d_GMB[MAXN * HP];        // {gate_w[j,HS+v]+gate_b[j], map_w[j,HS+v]}

// ---------------- PTX helpers (sm_100-baseline safe) ----------------
__device__ __forceinline__ uint32_t smem_u32(const void* p) {
    uint32_t a;
    asm("{ .reg .u64 t; cvta.to.shared.u64 t, %1; cvt.u32.u64 %0, t; }" : "=r"(a) : "l"(p));
    return a;
}
__device__ __forceinline__ void cpasync16(uint32_t dst, const void* src) {
    asm volatile("cp.async.cg.shared.global [%0], [%1], 16;" :: "r"(dst), "l"(src) : "memory");
}
#define CP_COMMIT() asm volatile("cp.async.commit_group;" ::: "memory")
#define CP_WAIT1()  asm volatile("cp.async.wait_group 1;" ::: "memory")

__device__ __forceinline__ void ldsm4(uint32_t& r0, uint32_t& r1, uint32_t& r2, uint32_t& r3,
                                      uint32_t addr) {
    asm volatile("ldmatrix.sync.aligned.m8n8.x4.shared.b16 {%0,%1,%2,%3}, [%4];"
                 : "=r"(r0), "=r"(r1), "=r"(r2), "=r"(r3) : "r"(addr));
}
__device__ __forceinline__ void mma_f16(float& c0, float& c1, float& c2, float& c3,
                                        uint32_t a0, uint32_t a1, uint32_t a2, uint32_t a3,
                                        uint32_t b0, uint32_t b1) {
    asm volatile("mma.sync.aligned.m16n8k16.row.col.f32.f16.f16.f32 "
                 "{%0,%1,%2,%3}, {%4,%5,%6,%7}, {%8,%9}, {%0,%1,%2,%3};"
                 : "+f"(c0), "+f"(c1), "+f"(c2), "+f"(c3)
                 : "r"(a0), "r"(a1), "r"(a2), "r"(a3), "r"(b0), "r"(b1));
}
__device__ __forceinline__ float sigmoidf_(float x) { return 1.f / (1.f + __expf(-x)); }

// ---------------- weight / table packing ----------------
__global__ void pack_whh_kernel(const float* __restrict__ w_hh) {
    int idx = blockIdx.x * blockDim.x + threadIdx.x;
    if (idx >= N1P * HP) return;
    int np = idx >> 9, kk = idx & 511;
    int g = np >> 9, j = np & 511;
    float v = (j < HS && kk < HS) ? w_hh[(g * HS + j) * HS + kk] : 0.f;
    d_Whh2[idx] = __float2half_rn(v);
}
__global__ void pack_w2_kernel(const float* __restrict__ gate_w,
                               const float* __restrict__ map_w) {
    int idx = blockIdx.x * blockDim.x + threadIdx.x;
    if (idx >= N2P * HP) return;
    int np = idx >> 9, kk = idx & 511;
    int j = np & 511;
    float v = 0.f;
    if (j < HS && kk < HS)
        v = (np < 512) ? gate_w[j * VS + kk] : map_w[j * VS + kk];
    d_W22[idx] = __float2half_rn(v);
}
__global__ void pack_tables_kernel(const float* __restrict__ w_ih,
                                   const float* __restrict__ b_ih,
                                   const float* __restrict__ b_hh,
                                   const float* __restrict__ gate_w,
                                   const float* __restrict__ gate_b,
                                   const float* __restrict__ map_w) {
    int idx = blockIdx.x * blockDim.x + threadIdx.x;
    if (idx < NVTT * HP) {
        int t = idx >> 9, j = idx & 511;
        float4 r = make_float4(0.f, 0.f, 0.f, 0.f);
        if (j < HS) {
            r.x = w_ih[(size_t)j * NVTT + t]            + b_ih[j]          + b_hh[j];
            r.y = w_ih[(size_t)(HS + j) * NVTT + t]     + b_ih[HS + j]     + b_hh[HS + j];
            r.z = w_ih[(size_t)(2 * HS + j) * NVTT + t] + b_ih[2 * HS + j];
            r.w = b_hh[2 * HS + j];
        }
        d_WIB[idx] = r;
    }
    if (idx < MAXN * HP) {
        int v = idx >> 9, j = idx & 511;
        float2 r = make_float2(0.f, 0.f);
        if (j < HS) {
            r.x = gate_w[(size_t)j * VS + HS + v] + gate_b[j];
            r.y = map_w[(size_t)j * VS + HS + v];
        }
        d_GMB[idx] = r;
    }
}

// ---------------- fp16 HMMA GEMM, BM=64, 128 threads, 3-stage ----------------
// 4 warps in 2x2: warpM = wid&1 (32 rows each), warpN = wid>>1 (BN/2 cols each)
template <int BN>
__global__ void __launch_bounds__(128, (BN == 64) ? 4 : 3)
gemm_tc(const __half* __restrict__ A, const __half* __restrict__ W,
        float* __restrict__ C, int ldc) {
    constexpr int BM = 64;
    constexpr int WN = BN / 2;          // 64 or 32
    constexpr int NI = WN / 8;          // 8 or 4
    constexpr int NC = HP / 64;         // 8 K-chunks
    constexpr int ABYTES = BM * 128;    // 8 KB
    constexpr int STAGE = (BM + BN) * 128;

    extern __shared__ char dynraw[];
    const uint32_t sbase = smem_u32(dynraw);

    const int tid  = threadIdx.x;
    const int wid  = tid >> 5;
    const int lane = tid & 31;
    const int warpM = wid & 1;
    const int warpN = wid >> 1;
    const int rowBase = blockIdx.y * BM;
    const int colBase = blockIdx.x * BN;

    const __half* Ab = A + (size_t)rowBase * HP;
    const __half* Wb = W + (size_t)colBase * HP;

    const uint32_t xmask = (uint32_t)((lane & 7) << 4);
    const int a_row = warpM * 32 + (lane & 15);
    const uint32_t a_coff = (uint32_t)((lane >> 4) << 4);
    const int b_row = warpN * WN + (lane & 7) + ((lane >> 4) & 1) * 8;
    const uint32_t b_coff = (uint32_t)(((lane >> 3) & 1) << 4);

    float acc[2][NI][4];
    #pragma unroll
    for (int i = 0; i < 2; i++)
        #pragma unroll
        for (int j = 0; j < NI; j++)
            #pragma unroll
            for (int q = 0; q < 4; q++) acc[i][j][q] = 0.f;

    auto load_chunk = [&](int c, int s) {
        uint32_t abase = sbase + s * STAGE;
        uint32_t bbase = abase + ABYTES;
        const __half* ga = Ab + c * 64;
        const __half* gw = Wb + c * 64;
        #pragma unroll
        for (int i = 0; i < (BM * 8) / 128; i++) {       // A: BM*8 16B ops
            int t = tid + i * 128;
            int row = t >> 3, kk = t & 7;
            cpasync16(abase + row * 128 + ((kk * 16) ^ ((row & 7) << 4)),
                      ga + (size_t)row * HP + kk * 8);
        }
        #pragma unroll
        for (int i = 0; i < (BN * 8) / 128; i++) {       // B: BN*8 16B ops
            int t = tid + i * 128;
            int row = t >> 3, kk = t & 7;
            cpasync16(bbase + row * 128 + ((kk * 16) ^ ((row & 7) << 4)),
                      gw + (size_t)row * HP + kk * 8);
        }
    };

    auto compute = [&](int s) {
        uint32_t abase = sbase + s * STAGE;
        uint32_t bbase = abase + ABYTES;
        #pragma unroll
        for (int kk = 0; kk < 4; kk++) {
            uint32_t kbyte = kk * 32;
            uint32_t af[2][4];
            #pragma unroll
            for (int mi = 0; mi < 2; mi++) {
                uint32_t addr = abase + (a_row + mi * 16) * 128 + ((kbyte + a_coff) ^ xmask);
                ldsm4(af[mi][0], af[mi][1], af[mi][2], af[mi][3], addr);
            }
            uint32_t bf[NI][2];
            #pragma unroll
            for (int nb = 0; nb < NI / 2; nb++) {
                uint32_t addr = bbase + (b_row + nb * 16) * 128 + ((kbyte + b_coff) ^ xmask);
                ldsm4(bf[nb * 2][0], bf[nb * 2][1], bf[nb * 2 + 1][0], bf[nb * 2 + 1][1], addr);
            }
            #pragma unroll
            for (int mi = 0; mi < 2; mi++)
                #pragma unroll
                for (int ni = 0; ni < NI; ni++)
                    mma_f16(acc[mi][ni][0], acc[mi][ni][1], acc[mi][ni][2], acc[mi][ni][3],
                            af[mi][0], af[mi][1], af[mi][2], af[mi][3],
                            bf[ni][0], bf[ni][1]);
        }
    };

    // 3-stage pipeline, prefetch depth 2
    load_chunk(0, 0); CP_COMMIT();
    load_chunk(1, 1); CP_COMMIT();

    #pragma unroll 1
    for (int c = 0; c < NC; c++) {
        CP_WAIT1();
        __syncthreads();
        if (c + 2 < NC) load_chunk(c + 2, (c + 2) % 3);
        CP_COMMIT();
        compute(c % 3);
        __syncthreads();
    }

    #pragma unroll
    for (int mi = 0; mi < 2; mi++) {
        int r0 = rowBase + warpM * 32 + mi * 16 + (lane >> 2);
        #pragma unroll
        for (int ni = 0; ni < NI; ni++) {
            int cc = colBase + warpN * WN + ni * 8 + (lane & 3) * 2;
            *reinterpret_cast<float2*>(C + (size_t)r0 * ldc + cc) =
                make_float2(acc[mi][ni][0], acc[mi][ni][1]);
            *reinterpret_cast<float2*>(C + (size_t)(r0 + 8) * ldc + cc) =
                make_float2(acc[mi][ni][2], acc[mi][ni][3]);
        }
    }
}

// ---------------- elementwise kernels (R7 shapes), b0 = half offset ----------------

// step-0 GRU (gh = 0, h = 0)
__global__ void init0_kernel(const int* __restrict__ node_types, int b0) {
    int b = blockIdx.x + b0;
    int j = threadIdx.x;
    __shared__ int st;
    if (j == 0) st = node_types[b * MAXN];
    __syncthreads();
    float hv = 0.f;
    if (j < HS) {
        float4 wib = d_WIB[st * HP + j];
        float r = sigmoidf_(wib.x);
        float z = sigmoidf_(wib.y);
        float n = tanhf(wib.z + r * wib.w);
        hv = (1.f - z) * n;
        d_hv[b * HP + j] = hv;
    }
    d_A2[b * HP + j] = __float2half_rn(j < HS ? hv : 0.f);
}

// GRU epilogue: hv from GH ; A2 = fp16(hv)
__global__ void epi1_kernel(const int* __restrict__ node_types, int v, int b0) {
    int b = blockIdx.x + b0;
    int j = threadIdx.x;
    __shared__ int st;
    if (j == 0) st = node_types[b * MAXN + v];
    __syncthreads();
    float hv = 0.f;
    if (j < HS) {
        float4 wib = d_WIB[st * HP + j];
        const float* gh = d_GH + (size_t)b * N1P;
        float r = sigmoidf_(wib.x + gh[j]);
        float z = sigmoidf_(wib.y + gh[512 + j]);
        float n = tanhf(wib.z + r * (gh[1024 + j] + wib.w));
        float h = d_Hin[b * HP + j];
        hv = (1.f - z) * n + z * h;
        d_hv[b * HP + j] = hv;
    }
    d_A2[b * HP + j] = __float2half_rn(j < HS ? hv : 0.f);
}

// fused gate/map + next-step h_in
__global__ void epi2hin_kernel(const float* __restrict__ adj, int v, int b0) {
    int b = blockIdx.x + b0;
    int j = threadIdx.x;
    __shared__ float sa[MAXN];
    if (j < MAXN) sa[j] = adj[(size_t)(b * MAXN + v + 1) * MAXN + j];
    __syncthreads();
    float acc = 0.f;
    if (j < HS) {
        float2 gmb = d_GMB[v * HP + j];
        const float* gm = d_GM + (size_t)b * N2P;
        float g = sigmoidf_(gm[j] + gmb.x);
        float m = gm[512 + j] + gmb.y;
        float Mv = g * m;
        float* Mb = d_M + (size_t)b * MAXN * HS + j;
        Mb[v * HS] = Mv;
        acc = sa[v] * Mv;
        for (int n = 0; n < v; n++) {
            float a = sa[n];
            if (a != 0.f) acc += a * Mb[n * HS];
        }
        d_Hin[b * HP + j] = acc;
    }
    d_A2[b * HP + j] = __float2half_rn(j < HS ? acc : 0.f);
}

// ---------------- final head ----------------
__global__ void final_kernel(const float* __restrict__ fc1_w,
                             const float* __restrict__ fc1_b,
                             const float* __restrict__ fc2_w,
                             const float* __restrict__ fc2_b,
                             float* __restrict__ out) {
    int b = blockIdx.x;
    __shared__ float sh[HS];
    for (int j = threadIdx.x; j < HS; j += blockDim.x)
        sh[j] = d_hv[(size_t)b * HP + j];
    __syncthreads();
    int o = threadIdx.x;
    if (o < 2 * NZ) {
        const float* w;
        float bias;
        if (o < NZ) { w = fc1_w + (size_t)o * HS;        bias = fc1_b[o]; }
        else        { w = fc2_w + (size_t)(o - NZ) * HS; bias = fc2_b[o - NZ]; }
        float acc = bias;
        #pragma unroll 4
        for (int k = 0; k < HS; k++) acc += w[k] * sh[k];
        out[(size_t)b * (2 * NZ) + o] = acc;
    }
}

// ---------------- launch ----------------
extern "C" void kernel_launch(void* const* d_in, const int* in_sizes, int n_in,
                              void* d_out, int out_size) {
    const int*   node_types = (const int*)  d_in[0];
    const float* adj        = (const float*)d_in[1];
    const float* w_ih       = (const float*)d_in[2];
    const float* w_hh       = (const float*)d_in[3];
    const float* b_ih       = (const float*)d_in[4];
    const float* b_hh       = (const float*)d_in[5];
    const float* gate_w     = (const float*)d_in[6];
    const float* gate_b     = (const float*)d_in[7];
    const float* map_w      = (const float*)d_in[8];
    const float* fc1_w      = (const float*)d_in[9];
    const float* fc1_b      = (const float*)d_in[10];
    const float* fc2_w      = (const float*)d_in[11];
    const float* fc2_b      = (const float*)d_in[12];
    float* out = (float*)d_out;

    // streams/events created once, host-side only (first call is outside capture)
    static cudaStream_t s1 = nullptr, s2 = nullptr;
    static cudaEvent_t ev0 = nullptr, ev1 = nullptr, ev2 = nullptr;
    if (s1 == nullptr) {
        cudaStreamCreateWithFlags(&s1, cudaStreamNonBlocking);
        cudaStreamCreateWithFlags(&s2, cudaStreamNonBlocking);
        cudaEventCreateWithFlags(&ev0, cudaEventDisableTiming);
        cudaEventCreateWithFlags(&ev1, cudaEventDisableTiming);
        cudaEventCreateWithFlags(&ev2, cudaEventDisableTiming);
    }

    void *pA2_, *pWhh2_, *pW22_, *pGH_, *pGM_;
    cudaGetSymbolAddress(&pA2_,   d_A2);
    cudaGetSymbolAddress(&pWhh2_, d_Whh2);
    cudaGetSymbolAddress(&pW22_,  d_W22);
    cudaGetSymbolAddress(&pGH_,   d_GH);
    cudaGetSymbolAddress(&pGM_,   d_GM);
    const __half* pA2   = (const __half*)pA2_;
    const __half* pWhh2 = (const __half*)pWhh2_;
    const __half* pW22  = (const __half*)pW22_;
    float* pGH = (float*)pGH_;
    float* pGM = (float*)pGM_;

    const int smem1 = 3 * (64 + 128) * 128;   // 72 KB -> 3 CTAs/SM
    const int smem2 = 3 * (64 + 64) * 128;    // 48 KB -> 4 CTAs/SM
    cudaFuncSetAttribute(gemm_tc<128>, cudaFuncAttributeMaxDynamicSharedMemorySize, smem1);
    cudaFuncSetAttribute(gemm_tc<64>,  cudaFuncAttributeMaxDynamicSharedMemorySize, smem2);

    // packs on the base stream
    pack_whh_kernel<<<(N1P * HP + 255) / 256, 256>>>(w_hh);
    pack_w2_kernel<<<(N2P * HP + 255) / 256, 256>>>(gate_w, map_w);
    pack_tables_kernel<<<(MAXN * HP + 255) / 256, 256>>>(w_ih, b_ih, b_hh,
                                                         gate_w, gate_b, map_w);
    cudaEventRecord(ev0, 0);
    cudaStreamWaitEvent(s1, ev0, 0);
    cudaStreamWaitEvent(s2, ev0, 0);

    // half-batch grids (BM = 64)
    dim3 g1h(N1P / 128, HB / 64);   // 12 x 16 = 192 blocks
    dim3 g2h(N2P / 64,  HB / 64);   // 16 x 16 = 256 blocks

    cudaStream_t ss[2] = {s1, s2};
    for (int h = 0; h < 2; h++) {
        cudaStream_t st = ss[h];
        int b0 = h * HB;
        const __half* A2h = pA2 + (size_t)b0 * HP;
        float* GHh = pGH + (size_t)b0 * N1P;
        float* GMh = pGM + (size_t)b0 * N2P;
        init0_kernel<<<HB, 512, 0, st>>>(node_types, b0);
        for (int v = 0; v < MAXN - 1; v++) {
            gemm_tc<64><<<g2h, 128, smem2, st>>>(A2h, pW22, GMh, N2P);
            epi2hin_kernel<<<HB, 512, 0, st>>>(adj, v, b0);
            gemm_tc<128><<<g1h, 128, smem1, st>>>(A2h, pWhh2, GHh, N1P);
            epi1_kernel<<<HB, 512, 0, st>>>(node_types, v + 1, b0);
        }
    }

    cudaEventRecord(ev1, s1);
    cudaEventRecord(ev2, s2);
    cudaStreamWaitEvent(0, ev1, 0);
    cudaStreamWaitEvent(0, ev2, 0);
    final_kernel<<<BB, 128>>>(fc1_w, fc1_b, fc2_w, fc2_b, out);
}

// round 14
// speedup vs baseline: 1.0424x; 1.0424x over previous
#include <cuda_runtime.h>
#include <cuda_fp16.h>
#include <cstdint>

// ---------------- problem constants ----------------
#define BB   2048
#define HB   1024           // half batch
#define MAXN 16
#define NVTT 8
#define HS   501
#define VS   517
#define HP   512            // padded HS = K of all GEMMs (fp16 single-pass)
#define N1P  1536           // 3 gates * 512 (gate-INTERLEAVED rows: n' = 3j+g)
#define N2P  1024           // 2 * 512     (gate-INTERLEAVED rows: n' = 2j+g)
#define NZ   56

// ---------------- device scratch ----------------
__device__ __half d_A2v[BB * HP];          // fp16 hv operand (gemm2 input)
__device__ __half d_A2h[BB * HP];          // fp16 h_in operand (gemm1 input)
__device__ __half d_Whh2[N1P * HP];        // fp16 w_hh, rows n'=3j+g
__device__ __half d_W22[N2P * HP];         // fp16 [gate|map], rows n'=2j+g
__device__ float  d_Hin[BB * HP];
__device__ float  d_hv[BB * HP];
__device__ float  d_M[BB * MAXN * HP];     // PADDED stride 512
__device__ float4 d_WIB[NVTT * HP];        // {w_r+bi_r+bh_r, w_z+bi_z+bh_z, w_n+bi_n, bh_n}
__device__ float2 d_GMB[MAXN * HP];        // {gate_w[j,HS+v]+gate_b[j], map_w[j,HS+v]}

// ---------------- PTX helpers (sm_100-baseline safe) ----------------
__device__ __forceinline__ uint32_t smem_u32(const void* p) {
    uint32_t a;
    asm("{ .reg .u64 t; cvta.to.shared.u64 t, %1; cvt.u32.u64 %0, t; }" : "=r"(a) : "l"(p));
    return a;
}
__device__ __forceinline__ void cpasync16(uint32_t dst, const void* src) {
    asm volatile("cp.async.cg.shared.global [%0], [%1], 16;" :: "r"(dst), "l"(src) : "memory");
}
#define CP_COMMIT() asm volatile("cp.async.commit_group;" ::: "memory")
#define CP_WAIT1()  asm volatile("cp.async.wait_group 1;" ::: "memory")
#define CP_WAIT0()  asm volatile("cp.async.wait_group 0;" ::: "memory")

__device__ __forceinline__ void ldsm4(uint32_t& r0, uint32_t& r1, uint32_t& r2, uint32_t& r3,
                                      uint32_t addr) {
    asm volatile("ldmatrix.sync.aligned.m8n8.x4.shared.b16 {%0,%1,%2,%3}, [%4];"
                 : "=r"(r0), "=r"(r1), "=r"(r2), "=r"(r3) : "r"(addr));
}
__device__ __forceinline__ void mma_f16(float& c0, float& c1, float& c2, float& c3,
                                        uint32_t a0, uint32_t a1, uint32_t a2, uint32_t a3,
                                        uint32_t b0, uint32_t b1) {
    asm volatile("mma.sync.aligned.m16n8k16.row.col.f32.f16.f16.f32 "
                 "{%0,%1,%2,%3}, {%4,%5,%6,%7}, {%8,%9}, {%0,%1,%2,%3};"
                 : "+f"(c0), "+f"(c1), "+f"(c2), "+f"(c3)
                 : "r"(a0), "r"(a1), "r"(a2), "r"(a3), "r"(b0), "r"(b1));
}
__device__ __forceinline__ float sigmoidf_(float x) { return 1.f / (1.f + __expf(-x)); }

// ---------------- weight / table packing (gate-interleaved) ----------------
__global__ void pack_whh_kernel(const float* __restrict__ w_hh) {
    int idx = blockIdx.x * blockDim.x + threadIdx.x;
    if (idx >= N1P * HP) return;
    int np = idx >> 9, kk = idx & 511;
    int j = np / 3, g = np - j * 3;
    float v = (j < HS && kk < HS) ? w_hh[(g * HS + j) * HS + kk] : 0.f;
    d_Whh2[idx] = __float2half_rn(v);
}
__global__ void pack_w2_kernel(const float* __restrict__ gate_w,
                               const float* __restrict__ map_w) {
    int idx = blockIdx.x * blockDim.x + threadIdx.x;
    if (idx >= N2P * HP) return;
    int np = idx >> 9, kk = idx & 511;
    int j = np >> 1, g = np & 1;
    float v = 0.f;
    if (j < HS && kk < HS)
        v = (g == 0) ? gate_w[j * VS + kk] : map_w[j * VS + kk];
    d_W22[idx] = __float2half_rn(v);
}
__global__ void pack_tables_kernel(const float* __restrict__ w_ih,
                                   const float* __restrict__ b_ih,
                                   const float* __restrict__ b_hh,
                                   const float* __restrict__ gate_w,
                                   const float* __restrict__ gate_b,
                                   const float* __restrict__ map_w) {
    int idx = blockIdx.x * blockDim.x + threadIdx.x;
    if (idx < NVTT * HP) {
        int t = idx >> 9, j = idx & 511;
        float4 r = make_float4(0.f, 0.f, 0.f, 0.f);
        if (j < HS) {
            r.x = w_ih[(size_t)j * NVTT + t]            + b_ih[j]          + b_hh[j];
            r.y = w_ih[(size_t)(HS + j) * NVTT + t]     + b_ih[HS + j]     + b_hh[HS + j];
            r.z = w_ih[(size_t)(2 * HS + j) * NVTT + t] + b_ih[2 * HS + j];
            r.w = b_hh[2 * HS + j];
        }
        d_WIB[idx] = r;
    }
    if (idx < MAXN * HP) {
        int v = idx >> 9, j = idx & 511;
        float2 r = make_float2(0.f, 0.f);
        if (j < HS) {
            r.x = gate_w[(size_t)j * VS + HS + v] + gate_b[j];
            r.y = map_w[(size_t)j * VS + HS + v];
        }
        d_GMB[idx] = r;
    }
}

// ---------------- fused GEMM: BM=64, 128 threads, 3-stage, fused epilogue ----------------
// WHICH=1: gemm1 + GRU epilogue      (A=A2h, W=Whh2 interleaved, BN=96)
//          -> writes d_hv, d_A2v     (step index v = GRU step)
// WHICH=2: gemm2 + gate/map + hin    (A=A2v, W=W22 interleaved,  BN=64)
//          -> writes d_M[v], d_Hin, d_A2h  (v = current step; hin for v+1)
template <int BN, int WHICH>
__global__ void __launch_bounds__(128, 3)
gemm_fused(const __half* __restrict__ A, const __half* __restrict__ W,
           const int* __restrict__ node_types, const float* __restrict__ adj,
           int v, int b0) {
    constexpr int BM = 64;
    constexpr int WN = BN / 2;          // 48 or 32
    constexpr int NI = WN / 8;          // 6 or 4
    constexpr int NC = HP / 64;         // 8 K-chunks
    constexpr int ABYTES = BM * 128;    // 8 KB
    constexpr int STAGE = (BM + BN) * 128;
    constexpr int SP = BN + 4;          // fp32 stage stride

    extern __shared__ char dynraw[];
    const uint32_t sbase = smem_u32(dynraw);

    const int tid  = threadIdx.x;
    const int wid  = tid >> 5;
    const int lane = tid & 31;
    const int warpM = wid & 1;
    const int warpN = wid >> 1;
    const int rowBase = blockIdx.y * BM;

    const __half* Ab = A + (size_t)rowBase * HP;
    const __half* Wb = W + (size_t)(blockIdx.x * BN) * HP;

    const uint32_t xmask = (uint32_t)((lane & 7) << 4);
    const int a_row = warpM * 32 + (lane & 15);
    const uint32_t a_coff = (uint32_t)((lane >> 4) << 4);
    const int b_row = warpN * WN + (lane & 7) + ((lane >> 4) & 1) * 8;
    const uint32_t b_coff = (uint32_t)(((lane >> 3) & 1) << 4);

    float acc[2][NI][4];
    #pragma unroll
    for (int i = 0; i < 2; i++)
        #pragma unroll
        for (int j = 0; j < NI; j++)
            #pragma unroll
            for (int q = 0; q < 4; q++) acc[i][j][q] = 0.f;

    auto load_chunk = [&](int c, int s) {
        uint32_t abase = sbase + s * STAGE;
        uint32_t bbase = abase + ABYTES;
        const __half* ga = Ab + c * 64;
        const __half* gw = Wb + c * 64;
        #pragma unroll
        for (int i = 0; i < (BM * 8) / 128; i++) {
            int t = tid + i * 128;
            int row = t >> 3, kk = t & 7;
            cpasync16(abase + row * 128 + ((kk * 16) ^ ((row & 7) << 4)),
                      ga + (size_t)row * HP + kk * 8);
        }
        #pragma unroll
        for (int i = 0; i < (BN * 8) / 128; i++) {
            int t = tid + i * 128;
            int row = t >> 3, kk = t & 7;
            cpasync16(bbase + row * 128 + ((kk * 16) ^ ((row & 7) << 4)),
                      gw + (size_t)row * HP + kk * 8);
        }
    };

    auto compute = [&](int s) {
        uint32_t abase = sbase + s * STAGE;
        uint32_t bbase = abase + ABYTES;
        #pragma unroll
        for (int kk = 0; kk < 4; kk++) {
            uint32_t kbyte = kk * 32;
            uint32_t af[2][4];
            #pragma unroll
            for (int mi = 0; mi < 2; mi++) {
                uint32_t addr = abase + (a_row + mi * 16) * 128 + ((kbyte + a_coff) ^ xmask);
                ldsm4(af[mi][0], af[mi][1], af[mi][2], af[mi][3], addr);
            }
            uint32_t bf[NI][2];
            #pragma unroll
            for (int nb = 0; nb < NI / 2; nb++) {
                uint32_t addr = bbase + (b_row + nb * 16) * 128 + ((kbyte + b_coff) ^ xmask);
                ldsm4(bf[nb * 2][0], bf[nb * 2][1], bf[nb * 2 + 1][0], bf[nb * 2 + 1][1], addr);
            }
            #pragma unroll
            for (int mi = 0; mi < 2; mi++)
                #pragma unroll
                for (int ni = 0; ni < NI; ni++)
                    mma_f16(acc[mi][ni][0], acc[mi][ni][1], acc[mi][ni][2], acc[mi][ni][3],
                            af[mi][0], af[mi][1], af[mi][2], af[mi][3],
                            bf[ni][0], bf[ni][1]);
        }
    };

    load_chunk(0, 0); CP_COMMIT();
    load_chunk(1, 1); CP_COMMIT();

    #pragma unroll 1
    for (int c = 0; c < NC; c++) {
        CP_WAIT1();
        __syncthreads();
        if (c + 2 < NC) load_chunk(c + 2, (c + 2) % 3);
        CP_COMMIT();
        compute(c % 3);
        __syncthreads();
    }

    // ---- stage accumulators to fp32 smem ----
    CP_WAIT0();
    __syncthreads();
    float* st = reinterpret_cast<float*>(dynraw);
    #pragma unroll
    for (int mi = 0; mi < 2; mi++) {
        int r0 = warpM * 32 + mi * 16 + (lane >> 2);
        #pragma unroll
        for (int ni = 0; ni < NI; ni++) {
            int cc = warpN * WN + ni * 8 + (lane & 3) * 2;
            *reinterpret_cast<float2*>(st + r0 * SP + cc) =
                make_float2(acc[mi][ni][0], acc[mi][ni][1]);
            *reinterpret_cast<float2*>(st + (r0 + 8) * SP + cc) =
                make_float2(acc[mi][ni][2], acc[mi][ni][3]);
        }
    }
    __syncthreads();

    // ---- fused epilogue: thread -> (b_local = tid>>1, 16 j's) ----
    const int bl = tid >> 1;
    const int jh = (tid & 1) * 16;
    const int j0 = blockIdx.x * 32 + jh;          // 16 consecutive j's
    const int b  = b0 + rowBase + bl;             // global batch row

    if constexpr (WHICH == 2) {
        // gate/map -> M[b,v,j0..], then h_in(v+1), A2h
        float a[16];
        {
            const float4* ar = reinterpret_cast<const float4*>(
                adj + ((size_t)b * MAXN + v + 1) * MAXN);
            float4 a0_ = ar[0], a1_ = ar[1], a2_ = ar[2], a3_ = ar[3];
            a[0]=a0_.x; a[1]=a0_.y; a[2]=a0_.z; a[3]=a0_.w;
            a[4]=a1_.x; a[5]=a1_.y; a[6]=a1_.z; a[7]=a1_.w;
            a[8]=a2_.x; a[9]=a2_.y; a[10]=a2_.z; a[11]=a2_.w;
            a[12]=a3_.x; a[13]=a3_.y; a[14]=a3_.z; a[15]=a3_.w;
        }
        const float2* gmb = d_GMB + (size_t)v * HP + j0;
        float Mv[16];
        #pragma unroll
        for (int q = 0; q < 16; q++) {
            float2 t2 = gmb[q];
            float g = sigmoidf_(st[bl * SP + 2 * (jh + q)] + t2.x);
            float m = st[bl * SP + 2 * (jh + q) + 1] + t2.y;
            Mv[q] = (j0 + q < HS) ? g * m : 0.f;
        }
        float* Mb = d_M + (size_t)b * MAXN * HP;
        #pragma unroll
        for (int q = 0; q < 4; q++)
            *reinterpret_cast<float4*>(Mb + v * HP + j0 + 4 * q) =
                make_float4(Mv[4*q], Mv[4*q+1], Mv[4*q+2], Mv[4*q+3]);
        float hacc[16];
        float av_self = a[v];
        #pragma unroll
        for (int q = 0; q < 16; q++) hacc[q] = av_self * Mv[q];
        #pragma unroll 1
        for (int n = 0; n < v; n++) {
            float av = a[n];
            if (av != 0.f) {
                #pragma unroll
                for (int q = 0; q < 4; q++) {
                    float4 mvec = *reinterpret_cast<const float4*>(Mb + n * HP + j0 + 4 * q);
                    hacc[4*q]   += av * mvec.x;
                    hacc[4*q+1] += av * mvec.y;
                    hacc[4*q+2] += av * mvec.z;
                    hacc[4*q+3] += av * mvec.w;
                }
            }
        }
        float* hinp = d_Hin + (size_t)b * HP + j0;
        #pragma unroll
        for (int q = 0; q < 4; q++)
            *reinterpret_cast<float4*>(hinp + 4 * q) =
                make_float4(hacc[4*q], hacc[4*q+1], hacc[4*q+2], hacc[4*q+3]);
        __half2 h2[8];
        #pragma unroll
        for (int q = 0; q < 8; q++)
            h2[q] = __floats2half2_rn(hacc[2*q], hacc[2*q+1]);
        float4* a2p = reinterpret_cast<float4*>(d_A2h + (size_t)b * HP + j0);
        a2p[0] = reinterpret_cast<float4*>(h2)[0];
        a2p[1] = reinterpret_cast<float4*>(h2)[1];
    } else {
        // GRU: hv(v) from staged gates + WIB + Hin; writes d_hv, d_A2v
        int nt = __ldg(node_types + (size_t)b * MAXN + v);
        const float4* wib = d_WIB + (size_t)nt * HP + j0;
        const float* hinp = d_Hin + (size_t)b * HP + j0;
        float hh[16];
        #pragma unroll
        for (int q = 0; q < 4; q++) {
            float4 h4 = *reinterpret_cast<const float4*>(hinp + 4 * q);
            hh[4*q] = h4.x; hh[4*q+1] = h4.y; hh[4*q+2] = h4.z; hh[4*q+3] = h4.w;
        }
        float hv[16];
        #pragma unroll
        for (int q = 0; q < 16; q++) {
            float4 w = wib[q];
            float gr = st[bl * SP + 3 * (jh + q)];
            float gz = st[bl * SP + 3 * (jh + q) + 1];
            float gn = st[bl * SP + 3 * (jh + q) + 2];
            float r = sigmoidf_(w.x + gr);
            float z = sigmoidf_(w.y + gz);
            float n = tanhf(w.z + r * (gn + w.w));
            hv[q] = (1.f - z) * n + z * hh[q];
        }
        float* hvp = d_hv + (size_t)b * HP + j0;
        #pragma unroll
        for (int q = 0; q < 4; q++)
            *reinterpret_cast<float4*>(hvp + 4 * q) =
                make_float4(hv[4*q], hv[4*q+1], hv[4*q+2], hv[4*q+3]);
        __half2 h2[8];
        #pragma unroll
        for (int q = 0; q < 8; q++)
            h2[q] = __floats2half2_rn((j0 + 2*q     < HS) ? hv[2*q]   : 0.f,
                                      (j0 + 2*q + 1 < HS) ? hv[2*q+1] : 0.f);
        float4* a2p = reinterpret_cast<float4*>(d_A2v + (size_t)b * HP + j0);
        a2p[0] = reinterpret_cast<float4*>(h2)[0];
        a2p[1] = reinterpret_cast<float4*>(h2)[1];
    }
}

// ---------------- step-0 GRU (gh = 0, h = 0): hv0 + A2v ----------------
__global__ void init0_kernel(const int* __restrict__ node_types, int b0) {
    int b = blockIdx.x + b0;
    int j = threadIdx.x;
    __shared__ int st;
    if (j == 0) st = node_types[b * MAXN];
    __syncthreads();
    float hv = 0.f;
    if (j < HS) {
        float4 wib = d_WIB[st * HP + j];
        float r = sigmoidf_(wib.x);
        float z = sigmoidf_(wib.y);
        float n = tanhf(wib.z + r * wib.w);
        hv = (1.f - z) * n;
        d_hv[b * HP + j] = hv;
    }
    d_A2v[b * HP + j] = __float2half_rn(j < HS ? hv : 0.f);
}

// ---------------- final head ----------------
__global__ void final_kernel(const float* __restrict__ fc1_w,
                             const float* __restrict__ fc1_b,
                             const float* __restrict__ fc2_w,
                             const float* __restrict__ fc2_b,
                             float* __restrict__ out) {
    int b = blockIdx.x;
    __shared__ float sh[HS];
    for (int j = threadIdx.x; j < HS; j += blockDim.x)
        sh[j] = d_hv[(size_t)b * HP + j];
    __syncthreads();
    int o = threadIdx.x;
    if (o < 2 * NZ) {
        const float* w;
        float bias;
        if (o < NZ) { w = fc1_w + (size_t)o * HS;        bias = fc1_b[o]; }
        else        { w = fc2_w + (size_t)(o - NZ) * HS; bias = fc2_b[o - NZ]; }
        float acc = bias;
        #pragma unroll 4
        for (int k = 0; k < HS; k++) acc += w[k] * sh[k];
        out[(size_t)b * (2 * NZ) + o] = acc;
    }
}

// ---------------- launch ----------------
extern "C" void kernel_launch(void* const* d_in, const int* in_sizes, int n_in,
                              void* d_out, int out_size) {
    const int*   node_types = (const int*)  d_in[0];
    const float* adj        = (const float*)d_in[1];
    const float* w_ih       = (const float*)d_in[2];
    const float* w_hh       = (const float*)d_in[3];
    const float* b_ih       = (const float*)d_in[4];
    const float* b_hh       = (const float*)d_in[5];
    const float* gate_w     = (const float*)d_in[6];
    const float* gate_b     = (const float*)d_in[7];
    const float* map_w      = (const float*)d_in[8];
    const float* fc1_w      = (const float*)d_in[9];
    const float* fc1_b      = (const float*)d_in[10];
    const float* fc2_w      = (const float*)d_in[11];
    const float* fc2_b      = (const float*)d_in[12];
    float* out = (float*)d_out;

    static cudaStream_t s1 = nullptr, s2 = nullptr;
    static cudaEvent_t ev0 = nullptr, ev1 = nullptr, ev2 = nullptr;
    if (s1 == nullptr) {
        cudaStreamCreateWithFlags(&s1, cudaStreamNonBlocking);
        cudaStreamCreateWithFlags(&s2, cudaStreamNonBlocking);
        cudaEventCreateWithFlags(&ev0, cudaEventDisableTiming);
        cudaEventCreateWithFlags(&ev1, cudaEventDisableTiming);
        cudaEventCreateWithFlags(&ev2, cudaEventDisableTiming);
    }

    void *pA2v_, *pA2h_, *pWhh2_, *pW22_;
    cudaGetSymbolAddress(&pA2v_,  d_A2v);
    cudaGetSymbolAddress(&pA2h_,  d_A2h);
    cudaGetSymbolAddress(&pWhh2_, d_Whh2);
    cudaGetSymbolAddress(&pW22_,  d_W22);
    const __half* pA2v  = (const __half*)pA2v_;
    const __half* pA2h  = (const __half*)pA2h_;
    const __half* pWhh2 = (const __half*)pWhh2_;
    const __half* pW22  = (const __half*)pW22_;

    const int smem1 = 3 * (64 + 96) * 128;    // 60 KB -> 3 CTAs/SM
    const int smem2 = 3 * (64 + 64) * 128;    // 48 KB -> 3 CTAs/SM
    cudaFuncSetAttribute((const void*)gemm_fused<96, 1>,
                         cudaFuncAttributeMaxDynamicSharedMemorySize, smem1);
    cudaFuncSetAttribute((const void*)gemm_fused<64, 2>,
                         cudaFuncAttributeMaxDynamicSharedMemorySize, smem2);

    pack_whh_kernel<<<(N1P * HP + 255) / 256, 256>>>(w_hh);
    pack_w2_kernel<<<(N2P * HP + 255) / 256, 256>>>(gate_w, map_w);
    pack_tables_kernel<<<(MAXN * HP + 255) / 256, 256>>>(w_ih, b_ih, b_hh,
                                                         gate_w, gate_b, map_w);
    cudaEventRecord(ev0, 0);
    cudaStreamWaitEvent(s1, ev0, 0);
    cudaStreamWaitEvent(s2, ev0, 0);

    dim3 g1h(N1P / 96, HB / 64);    // 16 x 16 = 256 blocks
    dim3 g2h(N2P / 64, HB / 64);    // 16 x 16 = 256 blocks

    cudaStream_t ss[2] = {s1, s2};
    for (int h = 0; h < 2; h++) {
        cudaStream_t st = ss[h];
        int b0 = h * HB;
        const __half* A2vh = pA2v + (size_t)b0 * HP;
        const __half* A2hh = pA2h + (size_t)b0 * HP;
        init0_kernel<<<HB, 512, 0, st>>>(node_types, b0);
        for (int v = 0; v < MAXN - 1; v++) {
            gemm_fused<64, 2><<<g2h, 128, smem2, st>>>(A2vh, pW22, node_types, adj, v, b0);
            gemm_fused<96, 1><<<g1h, 128, smem1, st>>>(A2hh, pWhh2, node_types, adj, v + 1, b0);
        }
    }

    cudaEventRecord(ev1, s1);
    cudaEventRecord(ev2, s2);
    cudaStreamWaitEvent(0, ev1, 0);
    cudaStreamWaitEvent(0, ev2, 0);
    final_kernel<<<BB, 128>>>(fc1_w, fc1_b, fc2_w, fc2_b, out);
}